// round 1
// baseline (speedup 1.0000x reference)
#include <cuda_runtime.h>
#include <math.h>

#define B_SZ 2048
#define L_SZ 64
#define D_SZ 256
#define U_SZ 512

// Scratch for proj_h(+b1+b2): [B, U] fp32 = 4 MB (device global: allocation-free)
__device__ float g_ph[B_SZ * U_SZ];

// ---------------------------------------------------------------------------
// Kernel 1: g_ph[b][u] = hidden[b,:] . W2[:,u] + b1[u] + b2[u]
// Tiled SGEMM: BM=64, BN=64, BK=16, 256 threads, 4x4 thread tile.
// ---------------------------------------------------------------------------
__global__ void proj_h_kernel(const float* __restrict__ hidden,
                              const float* __restrict__ W2,
                              const float* __restrict__ b1,
                              const float* __restrict__ b2)
{
    __shared__ float As[16][65];   // As[k][m], padded to kill STS conflicts
    __shared__ float Bs[16][68];   // Bs[k][n]

    const int tid  = threadIdx.x;
    const int row0 = blockIdx.y * 64;
    const int col0 = blockIdx.x * 64;
    const int tr   = tid >> 4;     // 0..15
    const int tc   = tid & 15;     // 0..15

    float acc[4][4];
#pragma unroll
    for (int i = 0; i < 4; ++i)
#pragma unroll
        for (int j = 0; j < 4; ++j) acc[i][j] = 0.f;

    for (int k0 = 0; k0 < U_SZ; k0 += 16) {
        // Load A tile (hidden): k fast per thread for decent coalescing
#pragma unroll
        for (int t = 0; t < 4; ++t) {
            int idx = tid + 256 * t;      // 0..1023
            int k = idx & 15;
            int m = idx >> 4;             // 0..63
            As[k][m] = hidden[(size_t)(row0 + m) * U_SZ + k0 + k];
        }
        // Load B tile (W2): n fast -> coalesced
#pragma unroll
        for (int t = 0; t < 4; ++t) {
            int idx = tid + 256 * t;
            int n = idx & 63;
            int k = idx >> 6;
            Bs[k][n] = W2[(size_t)(k0 + k) * U_SZ + col0 + n];
        }
        __syncthreads();

#pragma unroll
        for (int k = 0; k < 16; ++k) {
            float a[4], bb[4];
#pragma unroll
            for (int i = 0; i < 4; ++i) a[i] = As[k][tr * 4 + i];
#pragma unroll
            for (int j = 0; j < 4; ++j) bb[j] = Bs[k][tc * 4 + j];
#pragma unroll
            for (int i = 0; i < 4; ++i)
#pragma unroll
                for (int j = 0; j < 4; ++j)
                    acc[i][j] = fmaf(a[i], bb[j], acc[i][j]);
        }
        __syncthreads();
    }

#pragma unroll
    for (int i = 0; i < 4; ++i) {
        int m = row0 + tr * 4 + i;
#pragma unroll
        for (int j = 0; j < 4; ++j) {
            int n = col0 + tc * 4 + j;
            g_ph[(size_t)m * U_SZ + n] = acc[i][j] + b1[n] + b2[n];
        }
    }
}

// ---------------------------------------------------------------------------
// Kernel 2: fused attention per batch row b (one CTA each).
//   logits[l] = sum_u V[u] * tanh( F[l,:] . W1[:,u] + ph[b,u] )
//   w = softmax(logits);  ctx[d] = sum_l w[l] * F[l,d]
// 256 threads: ty = l-group (8 warps x 8 rows), tx = u-group (32 lanes x 4 u),
// 4 passes over u (128 u per pass). Score tensor never leaves registers.
// ---------------------------------------------------------------------------
__global__ void __launch_bounds__(256, 2)
attn_kernel(const float* __restrict__ features,
            const float* __restrict__ W1,
            const float* __restrict__ V,
            float* __restrict__ ctx_out,   // [B, 256] or null
            float* __restrict__ w_out)     // [B, 64]  or null
{
    extern __shared__ float Fs[];          // 64 x 256 fp32 = 64 KB
    __shared__ float ph_s[U_SZ];
    __shared__ float V_s[U_SZ];
    __shared__ float w_s[L_SZ];            // logits, then softmax weights
    __shared__ float red[4];

    const int b   = blockIdx.x;
    const int tid = threadIdx.x;
    const int tx  = tid & 31;
    const int ty  = tid >> 5;

    // Stage features[b] (coalesced float4)
    {
        const float4* fsrc = reinterpret_cast<const float4*>(
            features + (size_t)b * L_SZ * D_SZ);
        float4* fdst = reinterpret_cast<float4*>(Fs);
#pragma unroll
        for (int i = 0; i < 16; ++i)
            fdst[tid + 256 * i] = fsrc[tid + 256 * i];
    }
    ph_s[tid]       = g_ph[(size_t)b * U_SZ + tid];
    ph_s[tid + 256] = g_ph[(size_t)b * U_SZ + tid + 256];
    V_s[tid]        = V[tid];
    V_s[tid + 256]  = V[tid + 256];
    __syncthreads();

    const float* frow = Fs + ty * 8 * D_SZ;

    float plog[8];
#pragma unroll
    for (int i = 0; i < 8; ++i) plog[i] = 0.f;

    for (int p = 0; p < 4; ++p) {
        const int u0 = p * 128 + tx * 4;
        float acc[8][4];
#pragma unroll
        for (int i = 0; i < 8; ++i)
#pragma unroll
            for (int j = 0; j < 4; ++j) acc[i][j] = 0.f;

        // W1[d*512 + u0] viewed as float4
        const float4* wp = reinterpret_cast<const float4*>(W1 + u0);

#pragma unroll 4
        for (int d = 0; d < D_SZ; ++d) {
            float4 w = wp[(size_t)d * (U_SZ / 4)];
            float f[8];
#pragma unroll
            for (int i = 0; i < 8; ++i) f[i] = frow[i * D_SZ + d];  // smem broadcast
#pragma unroll
            for (int i = 0; i < 8; ++i) {
                acc[i][0] = fmaf(f[i], w.x, acc[i][0]);
                acc[i][1] = fmaf(f[i], w.y, acc[i][1]);
                acc[i][2] = fmaf(f[i], w.z, acc[i][2]);
                acc[i][3] = fmaf(f[i], w.w, acc[i][3]);
            }
        }

        float phv[4], vv[4];
#pragma unroll
        for (int j = 0; j < 4; ++j) { phv[j] = ph_s[u0 + j]; vv[j] = V_s[u0 + j]; }
#pragma unroll
        for (int i = 0; i < 8; ++i)
#pragma unroll
            for (int j = 0; j < 4; ++j) {
                float s = tanhf(acc[i][j] + phv[j]);
                plog[i] = fmaf(vv[j], s, plog[i]);
            }
    }

    // Reduce logits across lanes (lanes cover disjoint u); warp ty owns rows ty*8..ty*8+7
#pragma unroll
    for (int i = 0; i < 8; ++i) {
        float v = plog[i];
#pragma unroll
        for (int off = 16; off; off >>= 1)
            v += __shfl_xor_sync(0xffffffffu, v, off);
        if (tx == 0) w_s[ty * 8 + i] = v;
    }
    __syncthreads();

    // Softmax over L=64 (warps 0-1); bV is a constant shift -> softmax invariant
    float lv = (tid < 64) ? w_s[tid] : -1e30f;
    float m = lv;
#pragma unroll
    for (int off = 16; off; off >>= 1)
        m = fmaxf(m, __shfl_xor_sync(0xffffffffu, m, off));
    if (tid == 0)  red[0] = m;
    if (tid == 32) red[1] = m;
    __syncthreads();
    const float mx = fmaxf(red[0], red[1]);
    float e = (tid < 64) ? expf(lv - mx) : 0.f;
    float s = e;
#pragma unroll
    for (int off = 16; off; off >>= 1)
        s += __shfl_xor_sync(0xffffffffu, s, off);
    if (tid == 0)  red[2] = s;
    if (tid == 32) red[3] = s;
    __syncthreads();
    const float inv = 1.f / (red[2] + red[3]);
    if (tid < 64) w_s[tid] = e * inv;
    __syncthreads();

    // Context: thread tid owns feature dim d = tid
    float c = 0.f;
#pragma unroll
    for (int l = 0; l < L_SZ; ++l)
        c = fmaf(w_s[l], Fs[l * D_SZ + tid], c);

    if (ctx_out) ctx_out[(size_t)b * D_SZ + tid] = c;
    if (w_out && tid < L_SZ) w_out[(size_t)b * L_SZ + tid] = w_s[tid];
}

// ---------------------------------------------------------------------------
extern "C" void kernel_launch(void* const* d_in, const int* in_sizes, int n_in,
                              void* d_out, int out_size)
{
    const float* features = (const float*)d_in[0];
    const float* hidden   = (const float*)d_in[1];
    const float* W1       = (const float*)d_in[2];
    const float* b1       = (const float*)d_in[3];
    const float* W2       = (const float*)d_in[4];
    const float* b2       = (const float*)d_in[5];
    const float* V        = (const float*)d_in[6];
    // d_in[7] = bV: softmax is shift-invariant, so it never affects outputs.

    float* out = (float*)d_out;
    float* ctx_out = nullptr;
    float* w_out   = nullptr;
    const int CTX_N = B_SZ * D_SZ;   // 524288
    const int W_N   = B_SZ * L_SZ;   // 131072
    if (out_size >= CTX_N + W_N) { ctx_out = out; w_out = out + CTX_N; }
    else if (out_size == CTX_N)  { ctx_out = out; }
    else if (out_size == W_N)    { w_out = out; }
    else                         { ctx_out = out; }

    dim3 g1(U_SZ / 64, B_SZ / 64);
    proj_h_kernel<<<g1, 256>>>(hidden, W2, b1, b2);

    cudaFuncSetAttribute(attn_kernel,
                         cudaFuncAttributeMaxDynamicSharedMemorySize, 65536);
    attn_kernel<<<B_SZ, 256, 65536>>>(features, W1, V, ctx_out, w_out);
}